// round 1
// baseline (speedup 1.0000x reference)
#include <cuda_runtime.h>
#include <math.h>

// ---------------------------------------------------------------------------
// Problem constants (fixed by the dataset)
// ---------------------------------------------------------------------------
#define NMAX 50000
#define EMAX 800000
#define DDIM 128
#define HEADS 8
#define FIN 256
#define NCLS 40

// ---------------------------------------------------------------------------
// Device scratch (no allocations allowed)
// ---------------------------------------------------------------------------
__device__ float g_h  [NMAX * DDIM];
__device__ float g_ln [NMAX * DDIM];
__device__ float g_q  [NMAX * DDIM];
__device__ float g_k  [NMAX * DDIM];
__device__ float g_v  [NMAX * DDIM];
__device__ float g_agg[NMAX * DDIM];
__device__ float g_ff [NMAX * 2 * DDIM];
__device__ float g_sc [EMAX * HEADS];
__device__ float g_m  [NMAX * HEADS];
__device__ float g_den[NMAX * HEADS];

// ---------------------------------------------------------------------------
// Tiled fp32 GEMM: C[M,N] = op(A[M,K] @ B[K,N] + bias [+ Res])
// 64x64x16 block tile, 256 threads, 4x4 per thread.
// ---------------------------------------------------------------------------
template <bool RELU, bool RES>
__global__ __launch_bounds__(256) void gemm_bias_kernel(
    const float* __restrict__ A, const float* __restrict__ B,
    const float* __restrict__ bias, const float* __restrict__ Rsd,
    float* __restrict__ C, int M, int N, int K)
{
    __shared__ float As[16][64];
    __shared__ float Bs[16][68];

    const int tid = threadIdx.x;
    const int tx = tid & 15;          // output col group
    const int ty = tid >> 4;          // output row group
    const int row0 = blockIdx.y * 64;
    const int col0 = blockIdx.x * 64;
    const bool colsFull = (col0 + 64 <= N);

    // Load mapping
    const int aRow = tid >> 2;        // 0..63
    const int aCol = (tid & 3) * 4;   // 0,4,8,12
    const int bRow = tid >> 4;        // 0..15
    const int bCol = (tid & 15) * 4;  // 0..60

    float acc[4][4] = {};

    for (int k0 = 0; k0 < K; k0 += 16) {
        // --- A tile (64 x 16), stored transposed As[k][m]
        {
            int ar = row0 + aRow;
            float4 av = make_float4(0.f, 0.f, 0.f, 0.f);
            if (ar < M)
                av = *(const float4*)(A + (size_t)ar * K + k0 + aCol);
            As[aCol + 0][aRow] = av.x;
            As[aCol + 1][aRow] = av.y;
            As[aCol + 2][aRow] = av.z;
            As[aCol + 3][aRow] = av.w;
        }
        // --- B tile (16 x 64)
        {
            int br = k0 + bRow;       // K is always a multiple of 16
            if (colsFull) {
                float4 bv = *(const float4*)(B + (size_t)br * N + col0 + bCol);
                *(float4*)&Bs[bRow][bCol] = bv;
            } else {
                #pragma unroll
                for (int j = 0; j < 4; j++) {
                    int c = col0 + bCol + j;
                    Bs[bRow][bCol + j] = (c < N) ? B[(size_t)br * N + c] : 0.f;
                }
            }
        }
        __syncthreads();

        #pragma unroll
        for (int kk = 0; kk < 16; kk++) {
            float4 a = *(const float4*)&As[kk][ty * 4];
            float4 b = *(const float4*)&Bs[kk][tx * 4];
            acc[0][0] += a.x * b.x; acc[0][1] += a.x * b.y; acc[0][2] += a.x * b.z; acc[0][3] += a.x * b.w;
            acc[1][0] += a.y * b.x; acc[1][1] += a.y * b.y; acc[1][2] += a.y * b.z; acc[1][3] += a.y * b.w;
            acc[2][0] += a.z * b.x; acc[2][1] += a.z * b.y; acc[2][2] += a.z * b.z; acc[2][3] += a.z * b.w;
            acc[3][0] += a.w * b.x; acc[3][1] += a.w * b.y; acc[3][2] += a.w * b.z; acc[3][3] += a.w * b.w;
        }
        __syncthreads();
    }

    // --- Epilogue
    const int c0 = col0 + tx * 4;
    if (colsFull) {
        float4 bia = *(const float4*)(bias + c0);
        #pragma unroll
        for (int i = 0; i < 4; i++) {
            int r = row0 + ty * 4 + i;
            if (r >= M) break;
            float4 val;
            val.x = acc[i][0] + bia.x;
            val.y = acc[i][1] + bia.y;
            val.z = acc[i][2] + bia.z;
            val.w = acc[i][3] + bia.w;
            if (RELU) {
                val.x = fmaxf(val.x, 0.f); val.y = fmaxf(val.y, 0.f);
                val.z = fmaxf(val.z, 0.f); val.w = fmaxf(val.w, 0.f);
            }
            if (RES) {
                float4 rv = *(const float4*)(Rsd + (size_t)r * N + c0);
                val.x += rv.x; val.y += rv.y; val.z += rv.z; val.w += rv.w;
            }
            *(float4*)(C + (size_t)r * N + c0) = val;
        }
    } else {
        #pragma unroll
        for (int i = 0; i < 4; i++) {
            int r = row0 + ty * 4 + i;
            if (r >= M) break;
            #pragma unroll
            for (int j = 0; j < 4; j++) {
                int c = c0 + j;
                if (c >= N) continue;
                float val = acc[i][j] + bias[c];
                if (RELU) val = fmaxf(val, 0.f);
                if (RES)  val += Rsd[(size_t)r * N + c];
                C[(size_t)r * N + c] = val;
            }
        }
    }
}

// ---------------------------------------------------------------------------
// LayerNorm over D=128: one warp per row, 8 rows per block
// ---------------------------------------------------------------------------
__global__ void ln_kernel(const float* __restrict__ X, const float* __restrict__ g,
                          const float* __restrict__ b, float* __restrict__ Y, int n)
{
    int row = blockIdx.x * 8 + threadIdx.y;
    if (row >= n) return;
    int lane = threadIdx.x;
    float4 x = *(const float4*)(X + (size_t)row * DDIM + lane * 4);
    float s  = x.x + x.y + x.z + x.w;
    float ss = x.x * x.x + x.y * x.y + x.z * x.z + x.w * x.w;
    #pragma unroll
    for (int o = 16; o > 0; o >>= 1) {
        s  += __shfl_xor_sync(0xffffffffu, s, o);
        ss += __shfl_xor_sync(0xffffffffu, ss, o);
    }
    float mu  = s * (1.f / DDIM);
    float var = ss * (1.f / DDIM) - mu * mu;
    float rstd = rsqrtf(var + 1e-5f);
    float4 gv = *(const float4*)(g + lane * 4);
    float4 bv = *(const float4*)(b + lane * 4);
    float4 y;
    y.x = (x.x - mu) * rstd * gv.x + bv.x;
    y.y = (x.y - mu) * rstd * gv.y + bv.y;
    y.z = (x.z - mu) * rstd * gv.z + bv.z;
    y.w = (x.w - mu) * rstd * gv.w + bv.w;
    *(float4*)(Y + (size_t)row * DDIM + lane * 4) = y;
}

// ---------------------------------------------------------------------------
// Attention edge pipeline
// ---------------------------------------------------------------------------
__device__ __forceinline__ void atomicMaxF(float* addr, float v)
{
    if (v >= 0.f) atomicMax((int*)addr, __float_as_int(v));
    else          atomicMin((unsigned int*)addr, __float_as_uint(v));
}

__global__ void init_attn_kernel(float* __restrict__ m, float* __restrict__ den,
                                 float* __restrict__ agg, int nh, int nd)
{
    int t = blockIdx.x * blockDim.x + threadIdx.x;
    if (t < nd) agg[t] = 0.f;
    if (t < nh) { m[t] = -INFINITY; den[t] = 0.f; }
}

// scores[e,h] = dot(q[src], k[dst]) per head / 4 ; fused atomicMax into m
__global__ void scores_kernel(const float* __restrict__ q, const float* __restrict__ k,
                              const int* __restrict__ src, const int* __restrict__ dst,
                              float* __restrict__ scores, float* __restrict__ mbuf, int E)
{
    int e = blockIdx.x * 8 + threadIdx.y;
    if (e >= E) return;
    int lane = threadIdx.x;
    int s = src[e], d = dst[e];
    float4 qa = *(const float4*)(q + (size_t)s * DDIM + lane * 4);
    float4 ka = *(const float4*)(k + (size_t)d * DDIM + lane * 4);
    float p = qa.x * ka.x + qa.y * ka.y + qa.z * ka.z + qa.w * ka.w;
    p += __shfl_xor_sync(0xffffffffu, p, 1);
    p += __shfl_xor_sync(0xffffffffu, p, 2);
    if ((lane & 3) == 0) {
        int h = lane >> 2;
        float sc = p * 0.25f;  // 1/sqrt(16)
        scores[(size_t)e * HEADS + h] = sc;
        atomicMaxF(&mbuf[d * HEADS + h], sc);
    }
}

// ex = exp(score - m[dst]); denom[dst] += ex
__global__ void exp_kernel(float* __restrict__ scores, const int* __restrict__ dst,
                           const float* __restrict__ mbuf, float* __restrict__ den, int EH)
{
    int t = blockIdx.x * blockDim.x + threadIdx.x;
    if (t >= EH) return;
    int e = t >> 3, h = t & 7;
    int d = dst[e];
    float ex = __expf(scores[t] - mbuf[d * HEADS + h]);
    scores[t] = ex;
    atomicAdd(&den[d * HEADS + h], ex);
}

// agg[dst] += v[src] * (ex / denom[dst]) per head
__global__ void agg_kernel(const float* __restrict__ v, const float* __restrict__ scores,
                           const float* __restrict__ den, const int* __restrict__ src,
                           const int* __restrict__ dst, float* __restrict__ agg, int E)
{
    int e = blockIdx.x * 8 + threadIdx.y;
    if (e >= E) return;
    int lane = threadIdx.x;
    int s = src[e], d = dst[e];
    int h = lane >> 2;
    float w = scores[(size_t)e * HEADS + h] / den[d * HEADS + h];
    float4 vv = *(const float4*)(v + (size_t)s * DDIM + lane * 4);
    float* dp = agg + (size_t)d * DDIM + lane * 4;
    atomicAdd(dp + 0, vv.x * w);
    atomicAdd(dp + 1, vv.y * w);
    atomicAdd(dp + 2, vv.z * w);
    atomicAdd(dp + 3, vv.w * w);
}

// ---------------------------------------------------------------------------
// Host orchestration
// ---------------------------------------------------------------------------
extern "C" void kernel_launch(void* const* d_in, const int* in_sizes, int n_in,
                              void* d_out, int out_size)
{
    const float* x    = (const float*)d_in[0];
    const int*   esrc = (const int*)  d_in[1];
    const int*   edst = (const int*)  d_in[2];
    const float* Wi   = (const float*)d_in[3];
    const float* bi   = (const float*)d_in[4];
    const float* Wq   = (const float*)d_in[5];
    const float* bq   = (const float*)d_in[6];
    const float* Wk   = (const float*)d_in[7];
    const float* bk   = (const float*)d_in[8];
    const float* Wv   = (const float*)d_in[9];
    const float* bv   = (const float*)d_in[10];
    const float* Wo   = (const float*)d_in[11];
    const float* bo   = (const float*)d_in[12];
    const float* g1   = (const float*)d_in[13];
    const float* b1   = (const float*)d_in[14];
    const float* Wf1  = (const float*)d_in[15];
    const float* bf1  = (const float*)d_in[16];
    const float* Wf2  = (const float*)d_in[17];
    const float* bf2  = (const float*)d_in[18];
    const float* gout = (const float*)d_in[19];
    const float* boutg= (const float*)d_in[20];
    const float* Wout = (const float*)d_in[21];
    const float* bout = (const float*)d_in[22];

    const int Nn = in_sizes[0] / FIN;   // 50000
    const int Ee = in_sizes[1];         // 800000

    float *h, *ln, *q, *k, *v, *agg, *ff, *sc, *m, *den;
    cudaGetSymbolAddress((void**)&h,   g_h);
    cudaGetSymbolAddress((void**)&ln,  g_ln);
    cudaGetSymbolAddress((void**)&q,   g_q);
    cudaGetSymbolAddress((void**)&k,   g_k);
    cudaGetSymbolAddress((void**)&v,   g_v);
    cudaGetSymbolAddress((void**)&agg, g_agg);
    cudaGetSymbolAddress((void**)&ff,  g_ff);
    cudaGetSymbolAddress((void**)&sc,  g_sc);
    cudaGetSymbolAddress((void**)&m,   g_m);
    cudaGetSymbolAddress((void**)&den, g_den);

    const int mb = (Nn + 63) / 64;              // GEMM row blocks
    const dim3 gD(2, mb);                       // N=128 output
    const dim3 gF(4, mb);                       // N=256 output
    const dim3 gC(1, mb);                       // N=40  output
    const int lnBlocks   = (Nn + 7) / 8;
    const dim3 warpRows(32, 8);
    const int edgeBlocks = (Ee + 7) / 8;
    const int expBlocks  = (Ee * HEADS + 255) / 256;
    const int initBlocks = (Nn * DDIM + 255) / 256;

    // h = relu(x @ Wi + bi)
    gemm_bias_kernel<true, false><<<gD, 256>>>(x, Wi, bi, nullptr, h, Nn, DDIM, FIN);

    for (int i = 0; i < 5; i++) {
        const float* Wqi = Wq + (size_t)i * DDIM * DDIM;
        const float* Wki = Wk + (size_t)i * DDIM * DDIM;
        const float* Wvi = Wv + (size_t)i * DDIM * DDIM;
        const float* Woi = Wo + (size_t)i * DDIM * DDIM;
        const float* Wf1i = Wf1 + (size_t)i * DDIM * 2 * DDIM;
        const float* Wf2i = Wf2 + (size_t)i * 2 * DDIM * DDIM;

        // r = LN(h)
        ln_kernel<<<lnBlocks, warpRows>>>(h, g1 + i * DDIM, b1 + i * DDIM, ln, Nn);
        // q,k,v
        gemm_bias_kernel<false, false><<<gD, 256>>>(ln, Wqi, bq + i * DDIM, nullptr, q, Nn, DDIM, DDIM);
        gemm_bias_kernel<false, false><<<gD, 256>>>(ln, Wki, bk + i * DDIM, nullptr, k, Nn, DDIM, DDIM);
        gemm_bias_kernel<false, false><<<gD, 256>>>(ln, Wvi, bv + i * DDIM, nullptr, v, Nn, DDIM, DDIM);
        // edge softmax + aggregate
        init_attn_kernel<<<initBlocks, 256>>>(m, den, agg, Nn * HEADS, Nn * DDIM);
        scores_kernel<<<edgeBlocks, warpRows>>>(q, k, esrc, edst, sc, m, Ee);
        exp_kernel<<<expBlocks, 256>>>(sc, edst, m, den, Ee * HEADS);
        agg_kernel<<<edgeBlocks, warpRows>>>(v, sc, den, esrc, edst, agg, Ee);
        // h = h + agg @ Wo + bo
        gemm_bias_kernel<false, true><<<gD, 256>>>(agg, Woi, bo + i * DDIM, h, h, Nn, DDIM, DDIM);
        // FFN (note: reference reuses g1/b1 for the second norm)
        ln_kernel<<<lnBlocks, warpRows>>>(h, g1 + i * DDIM, b1 + i * DDIM, ln, Nn);
        gemm_bias_kernel<true, false><<<gF, 256>>>(ln, Wf1i, bf1 + i * 2 * DDIM, nullptr, ff, Nn, 2 * DDIM, DDIM);
        gemm_bias_kernel<false, true><<<gD, 256>>>(ff, Wf2i, bf2 + i * DDIM, h, h, Nn, DDIM, 2 * DDIM);
    }

    // mid = h
    cudaMemcpyAsync(d_out, h, (size_t)Nn * DDIM * sizeof(float), cudaMemcpyDeviceToDevice);
    // out = LN(h) @ Wout + bout
    ln_kernel<<<lnBlocks, warpRows>>>(h, gout, boutg, ln, Nn);
    gemm_bias_kernel<false, false><<<gC, 256>>>(ln, Wout, bout, nullptr,
                                                (float*)d_out + (size_t)Nn * DDIM, Nn, NCLS, DDIM);
}

// round 3
// speedup vs baseline: 1.4848x; 1.4848x over previous
#include <cuda_runtime.h>
#include <math.h>

// ---------------------------------------------------------------------------
// Problem constants
// ---------------------------------------------------------------------------
#define NMAX 50000
#define EMAX 800000
#define DDIM 128
#define HEADS 8
#define FIN 256
#define NCLS 40

// ---------------------------------------------------------------------------
// Device scratch (no allocations allowed)
// ---------------------------------------------------------------------------
__device__ float g_h  [NMAX * DDIM];
__device__ float g_ln [NMAX * DDIM];
__device__ float g_q  [NMAX * DDIM];
__device__ float g_k  [NMAX * DDIM];
__device__ float g_v  [NMAX * DDIM];
__device__ float g_agg[NMAX * DDIM];
__device__ float g_ff [NMAX * 2 * DDIM];
__device__ int   g_deg [NMAX];
__device__ int   g_cur [NMAX];
__device__ int   g_off [NMAX + 1];
__device__ int   g_srcs[EMAX];

// ---------------------------------------------------------------------------
// Tiled fp32 GEMM: C[M,N] = op(A[M,K] @ B[K,N] + bias [+ Res])
// 128x128x16 block tile, 256 threads, 8x8 per thread (2x2 of float4 frags)
// ---------------------------------------------------------------------------
template <bool RELU, bool RES>
__global__ __launch_bounds__(256) void gemm_bias_kernel(
    const float* __restrict__ A, const float* __restrict__ B,
    const float* __restrict__ bias, const float* __restrict__ Rsd,
    float* __restrict__ C, int M, int N, int K)
{
    __shared__ float As[16][132];
    __shared__ float Bs[16][132];

    const int tid = threadIdx.x;
    const int tx = tid & 15;
    const int ty = tid >> 4;
    const int row0 = blockIdx.y * 128;
    const int col0 = blockIdx.x * 128;
    const bool colsFull = (col0 + 128 <= N);

    float acc[8][8] = {};

    for (int k0 = 0; k0 < K; k0 += 16) {
        #pragma unroll
        for (int i = 0; i < 2; i++) {
            int idx = tid + i * 256;
            // A tile: 128 rows x 16 cols, stored transposed As[k][m]
            int r  = idx >> 2;
            int c4 = (idx & 3) * 4;
            int ar = row0 + r;
            float4 av = make_float4(0.f, 0.f, 0.f, 0.f);
            if (ar < M) av = *(const float4*)(A + (size_t)ar * K + k0 + c4);
            As[c4 + 0][r] = av.x;
            As[c4 + 1][r] = av.y;
            As[c4 + 2][r] = av.z;
            As[c4 + 3][r] = av.w;
            // B tile: 16 rows x 128 cols
            int br = idx >> 5;          // 0..15
            int bc = (idx & 31) * 4;    // 0..124
            if (colsFull) {
                float4 bv = *(const float4*)(B + (size_t)(k0 + br) * N + col0 + bc);
                *(float4*)&Bs[br][bc] = bv;
            } else {
                #pragma unroll
                for (int j = 0; j < 4; j++) {
                    int c = col0 + bc + j;
                    Bs[br][bc + j] = (c < N) ? B[(size_t)(k0 + br) * N + c] : 0.f;
                }
            }
        }
        __syncthreads();

        #pragma unroll
        for (int kk = 0; kk < 16; kk++) {
            float4 a0 = *(const float4*)&As[kk][ty * 4];
            float4 a1 = *(const float4*)&As[kk][64 + ty * 4];
            float4 b0 = *(const float4*)&Bs[kk][tx * 4];
            float4 b1 = *(const float4*)&Bs[kk][64 + tx * 4];
            float a[8] = {a0.x, a0.y, a0.z, a0.w, a1.x, a1.y, a1.z, a1.w};
            float b[8] = {b0.x, b0.y, b0.z, b0.w, b1.x, b1.y, b1.z, b1.w};
            #pragma unroll
            for (int i = 0; i < 8; i++)
                #pragma unroll
                for (int j = 0; j < 8; j++)
                    acc[i][j] += a[i] * b[j];
        }
        __syncthreads();
    }

    // --- Epilogue: rows {ty*4+i, 64+ty*4+i}, cols {tx*4+j, 64+tx*4+j}
    #pragma unroll
    for (int i = 0; i < 8; i++) {
        int r = row0 + (i < 4 ? ty * 4 + i : 64 + ty * 4 + (i - 4));
        if (r >= M) continue;
        int ai = i;
        if (colsFull) {
            #pragma unroll
            for (int half = 0; half < 2; half++) {
                int c = col0 + half * 64 + tx * 4;
                float4 bia = *(const float4*)(bias + c);
                float4 val;
                val.x = acc[ai][half * 4 + 0] + bia.x;
                val.y = acc[ai][half * 4 + 1] + bia.y;
                val.z = acc[ai][half * 4 + 2] + bia.z;
                val.w = acc[ai][half * 4 + 3] + bia.w;
                if (RELU) {
                    val.x = fmaxf(val.x, 0.f); val.y = fmaxf(val.y, 0.f);
                    val.z = fmaxf(val.z, 0.f); val.w = fmaxf(val.w, 0.f);
                }
                if (RES) {
                    float4 rv = *(const float4*)(Rsd + (size_t)r * N + c);
                    val.x += rv.x; val.y += rv.y; val.z += rv.z; val.w += rv.w;
                }
                *(float4*)(C + (size_t)r * N + c) = val;
            }
        } else {
            #pragma unroll
            for (int half = 0; half < 2; half++) {
                #pragma unroll
                for (int j = 0; j < 4; j++) {
                    int c = col0 + half * 64 + tx * 4 + j;
                    if (c >= N) continue;
                    float val = acc[ai][half * 4 + j] + bias[c];
                    if (RELU) val = fmaxf(val, 0.f);
                    if (RES)  val += Rsd[(size_t)r * N + c];
                    C[(size_t)r * N + c] = val;
                }
            }
        }
    }
}

// ---------------------------------------------------------------------------
// LayerNorm over D=128: one warp per row, 8 rows per block
// ---------------------------------------------------------------------------
__global__ void ln_kernel(const float* __restrict__ X, const float* __restrict__ g,
                          const float* __restrict__ b, float* __restrict__ Y, int n)
{
    int row = blockIdx.x * 8 + threadIdx.y;
    if (row >= n) return;
    int lane = threadIdx.x;
    float4 x = *(const float4*)(X + (size_t)row * DDIM + lane * 4);
    float s  = x.x + x.y + x.z + x.w;
    float ss = x.x * x.x + x.y * x.y + x.z * x.z + x.w * x.w;
    #pragma unroll
    for (int o = 16; o > 0; o >>= 1) {
        s  += __shfl_xor_sync(0xffffffffu, s, o);
        ss += __shfl_xor_sync(0xffffffffu, ss, o);
    }
    float mu  = s * (1.f / DDIM);
    float var = ss * (1.f / DDIM) - mu * mu;
    float rstd = rsqrtf(var + 1e-5f);
    float4 gv = *(const float4*)(g + lane * 4);
    float4 bv = *(const float4*)(b + lane * 4);
    float4 y;
    y.x = (x.x - mu) * rstd * gv.x + bv.x;
    y.y = (x.y - mu) * rstd * gv.y + bv.y;
    y.z = (x.z - mu) * rstd * gv.z + bv.z;
    y.w = (x.w - mu) * rstd * gv.w + bv.w;
    *(float4*)(Y + (size_t)row * DDIM + lane * 4) = y;
}

// ---------------------------------------------------------------------------
// CSR build (edges grouped by destination node) — once per launch
// ---------------------------------------------------------------------------
__global__ void hist_kernel(const int* __restrict__ dst, int* __restrict__ deg, int E)
{
    int t = blockIdx.x * blockDim.x + threadIdx.x;
    if (t < E) atomicAdd(&deg[dst[t]], 1);
}

__global__ void scan_kernel(const int* __restrict__ deg, int* __restrict__ off, int n)
{
    const int T = 1024;
    __shared__ int sm[T];
    int t = threadIdx.x;
    int chunk = (n + T - 1) / T;
    int b = t * chunk;
    int e = min(n, b + chunk);
    int s = 0;
    for (int i = b; i < e; i++) s += deg[i];
    sm[t] = s;
    __syncthreads();
    for (int o = 1; o < T; o <<= 1) {
        int add = (t >= o) ? sm[t - o] : 0;
        __syncthreads();
        sm[t] += add;
        __syncthreads();
    }
    int excl = (t > 0) ? sm[t - 1] : 0;
    for (int i = b; i < e; i++) { off[i] = excl; excl += deg[i]; }
    if (t == T - 1) off[n] = excl;
}

__global__ void scatter_kernel(const int* __restrict__ src, const int* __restrict__ dst,
                               int* __restrict__ cur, int* __restrict__ srcs, int E)
{
    int t = blockIdx.x * blockDim.x + threadIdx.x;
    if (t < E) {
        int p = atomicAdd(&cur[dst[t]], 1);
        srcs[p] = src[t];
    }
}

// ---------------------------------------------------------------------------
// Fused edge-softmax attention: warp per destination node, online softmax
// lanes 4h..4h+3 own head h (16 dims); k[d] kept in registers.
// ---------------------------------------------------------------------------
__global__ void attn_kernel(const float* __restrict__ q, const float* __restrict__ k,
                            const float* __restrict__ v, const int* __restrict__ off,
                            const int* __restrict__ srcs, float* __restrict__ agg, int n)
{
    int node = blockIdx.x * 8 + threadIdx.y;
    if (node >= n) return;
    int lane = threadIdx.x;

    float4 kf = *(const float4*)(k + (size_t)node * DDIM + lane * 4);
    int beg = off[node], end = off[node + 1];

    float m = -INFINITY, ssum = 0.f;
    float4 acc = make_float4(0.f, 0.f, 0.f, 0.f);

    for (int j = beg; j < end; j++) {
        int s = srcs[j];
        float4 qa = *(const float4*)(q + (size_t)s * DDIM + lane * 4);
        float p = qa.x * kf.x + qa.y * kf.y + qa.z * kf.z + qa.w * kf.w;
        p += __shfl_xor_sync(0xffffffffu, p, 1);
        p += __shfl_xor_sync(0xffffffffu, p, 2);
        p *= 0.25f;  // 1/sqrt(HD=16)

        float mn = fmaxf(m, p);
        float scale = __expf(m - mn);     // exp(-inf)=0 on first edge
        float w = __expf(p - mn);
        ssum = ssum * scale + w;

        float4 vv = *(const float4*)(v + (size_t)s * DDIM + lane * 4);
        acc.x = acc.x * scale + w * vv.x;
        acc.y = acc.y * scale + w * vv.y;
        acc.z = acc.z * scale + w * vv.z;
        acc.w = acc.w * scale + w * vv.w;
        m = mn;
    }

    float inv = (end > beg) ? 1.f / ssum : 0.f;
    float4 outv;
    outv.x = acc.x * inv; outv.y = acc.y * inv;
    outv.z = acc.z * inv; outv.w = acc.w * inv;
    *(float4*)(agg + (size_t)node * DDIM + lane * 4) = outv;
}

// ---------------------------------------------------------------------------
// Host orchestration
// ---------------------------------------------------------------------------
extern "C" void kernel_launch(void* const* d_in, const int* in_sizes, int n_in,
                              void* d_out, int out_size)
{
    const float* x    = (const float*)d_in[0];
    const int*   esrc = (const int*)  d_in[1];
    const int*   edst = (const int*)  d_in[2];
    const float* Wi   = (const float*)d_in[3];
    const float* bi   = (const float*)d_in[4];
    const float* Wq   = (const float*)d_in[5];
    const float* bq   = (const float*)d_in[6];
    const float* Wk   = (const float*)d_in[7];
    const float* bk   = (const float*)d_in[8];
    const float* Wv   = (const float*)d_in[9];
    const float* bv   = (const float*)d_in[10];
    const float* Wo   = (const float*)d_in[11];
    const float* bo   = (const float*)d_in[12];
    const float* g1   = (const float*)d_in[13];
    const float* b1   = (const float*)d_in[14];
    const float* Wf1  = (const float*)d_in[15];
    const float* bf1  = (const float*)d_in[16];
    const float* Wf2  = (const float*)d_in[17];
    const float* bf2  = (const float*)d_in[18];
    const float* gout = (const float*)d_in[19];
    const float* boutg= (const float*)d_in[20];
    const float* Wout = (const float*)d_in[21];
    const float* bout = (const float*)d_in[22];

    const int Nn = in_sizes[0] / FIN;   // 50000
    const int Ee = in_sizes[1];         // 800000

    float *h, *ln, *q, *k, *v, *agg, *ff;
    int *deg, *cur, *off, *srcs;
    cudaGetSymbolAddress((void**)&h,    g_h);
    cudaGetSymbolAddress((void**)&ln,   g_ln);
    cudaGetSymbolAddress((void**)&q,    g_q);
    cudaGetSymbolAddress((void**)&k,    g_k);
    cudaGetSymbolAddress((void**)&v,    g_v);
    cudaGetSymbolAddress((void**)&agg,  g_agg);
    cudaGetSymbolAddress((void**)&ff,   g_ff);
    cudaGetSymbolAddress((void**)&deg,  g_deg);
    cudaGetSymbolAddress((void**)&cur,  g_cur);
    cudaGetSymbolAddress((void**)&off,  g_off);
    cudaGetSymbolAddress((void**)&srcs, g_srcs);

    const int mb = (Nn + 127) / 128;
    const dim3 gD(1, mb);                       // N=128 output
    const dim3 gF(2, mb);                       // N=256 output
    const dim3 gC(1, mb);                       // N=40  output
    const int lnBlocks = (Nn + 7) / 8;
    const dim3 warpRows(32, 8);
    const int eBlocks = (Ee + 255) / 256;
    const int nodeBlocks = (Nn + 7) / 8;

    // ---- CSR build (once; reused by all 5 layers)
    cudaMemsetAsync(deg, 0, Nn * sizeof(int));
    hist_kernel<<<eBlocks, 256>>>(edst, deg, Ee);
    scan_kernel<<<1, 1024>>>(deg, off, Nn);
    cudaMemcpyAsync(cur, off, Nn * sizeof(int), cudaMemcpyDeviceToDevice);
    scatter_kernel<<<eBlocks, 256>>>(esrc, edst, cur, srcs, Ee);

    // h = relu(x @ Wi + bi)
    gemm_bias_kernel<true, false><<<gD, 256>>>(x, Wi, bi, nullptr, h, Nn, DDIM, FIN);

    for (int i = 0; i < 5; i++) {
        const float* Wqi  = Wq  + (size_t)i * DDIM * DDIM;
        const float* Wki  = Wk  + (size_t)i * DDIM * DDIM;
        const float* Wvi  = Wv  + (size_t)i * DDIM * DDIM;
        const float* Woi  = Wo  + (size_t)i * DDIM * DDIM;
        const float* Wf1i = Wf1 + (size_t)i * DDIM * 2 * DDIM;
        const float* Wf2i = Wf2 + (size_t)i * 2 * DDIM * DDIM;

        ln_kernel<<<lnBlocks, warpRows>>>(h, g1 + i * DDIM, b1 + i * DDIM, ln, Nn);
        gemm_bias_kernel<false, false><<<gD, 256>>>(ln, Wqi, bq + i * DDIM, nullptr, q, Nn, DDIM, DDIM);
        gemm_bias_kernel<false, false><<<gD, 256>>>(ln, Wki, bk + i * DDIM, nullptr, k, Nn, DDIM, DDIM);
        gemm_bias_kernel<false, false><<<gD, 256>>>(ln, Wvi, bv + i * DDIM, nullptr, v, Nn, DDIM, DDIM);

        attn_kernel<<<nodeBlocks, warpRows>>>(q, k, v, off, srcs, agg, Nn);

        gemm_bias_kernel<false, true><<<gD, 256>>>(agg, Woi, bo + i * DDIM, h, h, Nn, DDIM, DDIM);

        ln_kernel<<<lnBlocks, warpRows>>>(h, g1 + i * DDIM, b1 + i * DDIM, ln, Nn);
        gemm_bias_kernel<true, false><<<gF, 256>>>(ln, Wf1i, bf1 + i * 2 * DDIM, nullptr, ff, Nn, 2 * DDIM, DDIM);
        gemm_bias_kernel<false, true><<<gD, 256>>>(ff, Wf2i, bf2 + i * DDIM, h, h, Nn, DDIM, 2 * DDIM);
    }

    // mid = h
    cudaMemcpyAsync(d_out, h, (size_t)Nn * DDIM * sizeof(float), cudaMemcpyDeviceToDevice);
    // out = LN(h) @ Wout + bout
    ln_kernel<<<lnBlocks, warpRows>>>(h, gout, boutg, ln, Nn);
    gemm_bias_kernel<false, false><<<gC, 256>>>(ln, Wout, bout, nullptr,
                                                (float*)d_out + (size_t)Nn * DDIM, Nn, NCLS, DDIM);
}

// round 4
// speedup vs baseline: 1.9519x; 1.3146x over previous
#include <cuda_runtime.h>
#include <math.h>
#include <stdint.h>

// ---------------------------------------------------------------------------
// Problem constants
// ---------------------------------------------------------------------------
#define NMAX 50000
#define EMAX 800000
#define DDIM 128
#define HEADS 8
#define FIN 256
#define NCLS 40

// ---------------------------------------------------------------------------
// Device scratch
// ---------------------------------------------------------------------------
__device__ float g_h  [NMAX * DDIM];
__device__ float g_ln [NMAX * DDIM];
__device__ float g_q  [NMAX * DDIM];
__device__ float g_k  [NMAX * DDIM];
__device__ float g_v  [NMAX * DDIM];
__device__ float g_agg[NMAX * DDIM];
__device__ float g_ff [NMAX * 2 * DDIM];
__device__ int   g_deg [NMAX];
__device__ int   g_cur [NMAX];
__device__ int   g_off [NMAX + 1];
__device__ int   g_srcs[EMAX];

// ---------------------------------------------------------------------------
// TF32 helpers
// ---------------------------------------------------------------------------
__device__ __forceinline__ float f2tf32(float x)
{
    uint32_t r;
    asm("cvt.rna.tf32.f32 %0, %1;" : "=r"(r) : "f"(x));
    return __uint_as_float(r);
}

__device__ __forceinline__ void mma_tf32(float* d, const uint32_t* a, const uint32_t* b)
{
    asm volatile(
        "mma.sync.aligned.m16n8k8.row.col.f32.tf32.tf32.f32 "
        "{%0,%1,%2,%3}, {%4,%5,%6,%7}, {%8,%9}, {%0,%1,%2,%3};\n"
        : "+f"(d[0]), "+f"(d[1]), "+f"(d[2]), "+f"(d[3])
        : "r"(a[0]), "r"(a[1]), "r"(a[2]), "r"(a[3]), "r"(b[0]), "r"(b[1]));
}

// ---------------------------------------------------------------------------
// Tensor-core GEMM body (3xTF32 split, fp32-class accuracy)
// C[M,N] = op(A[M,K] @ B[K,N] + bias [+ Res]); K % 16 == 0.
// Block tile 128x128, 8 warps (4M x 2N), warp tile 32x64 (2 x 8 m16n8 frags).
// As: [m 0..127][hi k0..15 | lo k0..15 | pad], stride 36 floats.
// Bs: [hi k0..15 | lo k0..15 rows][n 0..127 | pad], stride 136 floats.
// ---------------------------------------------------------------------------
#define A_STRIDE 36
#define B_STRIDE 136

template <bool RELU, bool RES>
__device__ __forceinline__ void gemm_tc_body(
    const float* __restrict__ A, const float* __restrict__ B,
    const float* __restrict__ bias, const float* __restrict__ Rsd,
    float* __restrict__ C, int M, int N, int K)
{
    __shared__ float As[128 * A_STRIDE];
    __shared__ float Bs[32 * B_STRIDE];

    const int tid  = threadIdx.x;
    const int lane = tid & 31;
    const int wid  = tid >> 5;
    const int g    = lane >> 2;   // group id (row within frag)
    const int c    = lane & 3;    // thread-in-group (k index within frag)
    const int wm   = (wid >> 1) * 32;   // warp M offset within block
    const int wn   = (wid & 1) * 64;    // warp N offset within block

    const int row0 = blockIdx.y * 128;
    const int col0 = blockIdx.x * 128;
    const bool colsFull = (col0 + 128 <= N);

    // Loader mapping
    const int lam = (tid & 7) | ((tid >> 5) << 3);   // A row 0..63 (then +64)
    const int lak = ((tid >> 3) & 3) << 2;           // A k4: 0,4,8,12
    const int lbk = tid >> 4;                        // B k row 0..15
    const int lbn = (tid & 15) << 2;                 // B n: 0..60 (then +64)

    float acc[2][8][4] = {};

    for (int k0 = 0; k0 < K; k0 += 16) {
        // ---- A tile: 128 x 16, split into hi/lo
        #pragma unroll
        for (int half = 0; half < 2; half++) {
            int m  = lam + half * 64;
            int ar = row0 + m;
            float4 av = make_float4(0.f, 0.f, 0.f, 0.f);
            if (ar < M) av = *(const float4*)(A + (size_t)ar * K + k0 + lak);
            float4 hi, lo;
            hi.x = f2tf32(av.x); lo.x = av.x - hi.x;
            hi.y = f2tf32(av.y); lo.y = av.y - hi.y;
            hi.z = f2tf32(av.z); lo.z = av.z - hi.z;
            hi.w = f2tf32(av.w); lo.w = av.w - hi.w;
            *(float4*)&As[m * A_STRIDE + lak]      = hi;
            *(float4*)&As[m * A_STRIDE + 16 + lak] = lo;
        }
        // ---- B tile: 16 x 128, split into hi/lo
        #pragma unroll
        for (int half = 0; half < 2; half++) {
            int ncol = col0 + lbn + half * 64;
            float4 bv;
            if (colsFull) {
                bv = *(const float4*)(B + (size_t)(k0 + lbk) * N + ncol);
            } else {
                bv.x = (ncol + 0 < N) ? B[(size_t)(k0 + lbk) * N + ncol + 0] : 0.f;
                bv.y = (ncol + 1 < N) ? B[(size_t)(k0 + lbk) * N + ncol + 1] : 0.f;
                bv.z = (ncol + 2 < N) ? B[(size_t)(k0 + lbk) * N + ncol + 2] : 0.f;
                bv.w = (ncol + 3 < N) ? B[(size_t)(k0 + lbk) * N + ncol + 3] : 0.f;
            }
            float4 hi, lo;
            hi.x = f2tf32(bv.x); lo.x = bv.x - hi.x;
            hi.y = f2tf32(bv.y); lo.y = bv.y - hi.y;
            hi.z = f2tf32(bv.z); lo.z = bv.z - hi.z;
            hi.w = f2tf32(bv.w); lo.w = bv.w - hi.w;
            int p = lbn + half * 64;
            *(float4*)&Bs[lbk * B_STRIDE + p]        = hi;
            *(float4*)&Bs[(16 + lbk) * B_STRIDE + p] = lo;
        }
        __syncthreads();

        #pragma unroll
        for (int h = 0; h < 2; h++) {
            // --- A fragments (hi and lo)
            uint32_t aH[2][4], aL[2][4];
            #pragma unroll
            for (int t = 0; t < 2; t++) {
                int r  = (wm + 16 * t + g) * A_STRIDE;
                int r8 = (wm + 16 * t + g + 8) * A_STRIDE;
                int ch = 8 * h + c;
                aH[t][0] = __float_as_uint(As[r  + ch]);
                aH[t][1] = __float_as_uint(As[r8 + ch]);
                aH[t][2] = __float_as_uint(As[r  + ch + 4]);
                aH[t][3] = __float_as_uint(As[r8 + ch + 4]);
                aL[t][0] = __float_as_uint(As[r  + 16 + ch]);
                aL[t][1] = __float_as_uint(As[r8 + 16 + ch]);
                aL[t][2] = __float_as_uint(As[r  + 16 + ch + 4]);
                aL[t][3] = __float_as_uint(As[r8 + 16 + ch + 4]);
            }
            // --- B hi fragments
            uint32_t bF[8][2];
            {
                int rb0 = (8 * h + c) * B_STRIDE;
                int rb1 = (8 * h + 4 + c) * B_STRIDE;
                #pragma unroll
                for (int j = 0; j < 8; j++) {
                    int nIdx = wn + 8 * j + g;
                    bF[j][0] = __float_as_uint(Bs[rb0 + nIdx]);
                    bF[j][1] = __float_as_uint(Bs[rb1 + nIdx]);
                }
            }
            // passes: hi*hi and lo*hi
            #pragma unroll
            for (int t = 0; t < 2; t++)
                #pragma unroll
                for (int j = 0; j < 8; j++) {
                    mma_tf32(acc[t][j], aH[t], bF[j]);
                    mma_tf32(acc[t][j], aL[t], bF[j]);
                }
            // --- B lo fragments (overwrite)
            {
                int rb0 = (16 + 8 * h + c) * B_STRIDE;
                int rb1 = (16 + 8 * h + 4 + c) * B_STRIDE;
                #pragma unroll
                for (int j = 0; j < 8; j++) {
                    int nIdx = wn + 8 * j + g;
                    bF[j][0] = __float_as_uint(Bs[rb0 + nIdx]);
                    bF[j][1] = __float_as_uint(Bs[rb1 + nIdx]);
                }
            }
            // pass: hi*lo
            #pragma unroll
            for (int t = 0; t < 2; t++)
                #pragma unroll
                for (int j = 0; j < 8; j++)
                    mma_tf32(acc[t][j], aH[t], bF[j]);
        }
        __syncthreads();
    }

    // ---- Epilogue: thread owns rows {wm+16t+g, +8}, cols {wn+8j+2c, +1}
    #pragma unroll
    for (int t = 0; t < 2; t++) {
        #pragma unroll
        for (int rr = 0; rr < 2; rr++) {
            int r = row0 + wm + 16 * t + g + rr * 8;
            if (r >= M) continue;
            #pragma unroll
            for (int j = 0; j < 8; j++) {
                int cc = col0 + wn + 8 * j + 2 * c;
                if (cc >= N) continue;   // N is even -> cc+1 < N too
                float v0 = acc[t][j][rr * 2 + 0] + bias[cc];
                float v1 = acc[t][j][rr * 2 + 1] + bias[cc + 1];
                if (RELU) { v0 = fmaxf(v0, 0.f); v1 = fmaxf(v1, 0.f); }
                if (RES) {
                    float2 rv = *(const float2*)(Rsd + (size_t)r * N + cc);
                    v0 += rv.x; v1 += rv.y;
                }
                float2 out; out.x = v0; out.y = v1;
                *(float2*)(C + (size_t)r * N + cc) = out;
            }
        }
    }
}

template <bool RELU, bool RES>
__global__ __launch_bounds__(256, 2) void gemm_tc_kernel(
    const float* __restrict__ A, const float* __restrict__ B,
    const float* __restrict__ bias, const float* __restrict__ Rsd,
    float* __restrict__ C, int M, int N, int K)
{
    gemm_tc_body<RELU, RES>(A, B, bias, Rsd, C, M, N, K);
}

// q,k,v fused into one launch: blockIdx.z selects weight/bias/output
__global__ __launch_bounds__(256, 2) void gemm_qkv_kernel(
    const float* __restrict__ A,
    const float* __restrict__ Wq, const float* __restrict__ Wk, const float* __restrict__ Wv,
    const float* __restrict__ bq, const float* __restrict__ bk, const float* __restrict__ bv,
    float* __restrict__ q, float* __restrict__ k, float* __restrict__ v, int M)
{
    const float* B; const float* bias; float* C;
    if (blockIdx.z == 0)      { B = Wq; bias = bq; C = q; }
    else if (blockIdx.z == 1) { B = Wk; bias = bk; C = k; }
    else                      { B = Wv; bias = bv; C = v; }
    gemm_tc_body<false, false>(A, B, bias, nullptr, C, M, DDIM, DDIM);
}

// ---------------------------------------------------------------------------
// LayerNorm over D=128: one warp per row, 8 rows per block
// ---------------------------------------------------------------------------
__global__ void ln_kernel(const float* __restrict__ X, const float* __restrict__ g,
                          const float* __restrict__ b, float* __restrict__ Y, int n)
{
    int row = blockIdx.x * 8 + threadIdx.y;
    if (row >= n) return;
    int lane = threadIdx.x;
    float4 x = *(const float4*)(X + (size_t)row * DDIM + lane * 4);
    float s  = x.x + x.y + x.z + x.w;
    float ss = x.x * x.x + x.y * x.y + x.z * x.z + x.w * x.w;
    #pragma unroll
    for (int o = 16; o > 0; o >>= 1) {
        s  += __shfl_xor_sync(0xffffffffu, s, o);
        ss += __shfl_xor_sync(0xffffffffu, ss, o);
    }
    float mu  = s * (1.f / DDIM);
    float var = ss * (1.f / DDIM) - mu * mu;
    float rstd = rsqrtf(var + 1e-5f);
    float4 gv = *(const float4*)(g + lane * 4);
    float4 bv = *(const float4*)(b + lane * 4);
    float4 y;
    y.x = (x.x - mu) * rstd * gv.x + bv.x;
    y.y = (x.y - mu) * rstd * gv.y + bv.y;
    y.z = (x.z - mu) * rstd * gv.z + bv.z;
    y.w = (x.w - mu) * rstd * gv.w + bv.w;
    *(float4*)(Y + (size_t)row * DDIM + lane * 4) = y;
}

// ---------------------------------------------------------------------------
// CSR build (edges grouped by destination) — once per launch
// ---------------------------------------------------------------------------
__global__ void hist_kernel(const int* __restrict__ dst, int* __restrict__ deg, int E)
{
    int t = blockIdx.x * blockDim.x + threadIdx.x;
    if (t < E) atomicAdd(&deg[dst[t]], 1);
}

__global__ void scan_kernel(const int* __restrict__ deg, int* __restrict__ off, int n)
{
    const int T = 1024;
    __shared__ int sm[T];
    int t = threadIdx.x;
    int chunk = (n + T - 1) / T;
    int b = t * chunk;
    int e = min(n, b + chunk);
    int s = 0;
    for (int i = b; i < e; i++) s += deg[i];
    sm[t] = s;
    __syncthreads();
    for (int o = 1; o < T; o <<= 1) {
        int add = (t >= o) ? sm[t - o] : 0;
        __syncthreads();
        sm[t] += add;
        __syncthreads();
    }
    int excl = (t > 0) ? sm[t - 1] : 0;
    for (int i = b; i < e; i++) { off[i] = excl; excl += deg[i]; }
    if (t == T - 1) off[n] = excl;
}

__global__ void scatter_kernel(const int* __restrict__ src, const int* __restrict__ dst,
                               int* __restrict__ cur, int* __restrict__ srcs, int E)
{
    int t = blockIdx.x * blockDim.x + threadIdx.x;
    if (t < E) {
        int p = atomicAdd(&cur[dst[t]], 1);
        srcs[p] = src[t];
    }
}

// ---------------------------------------------------------------------------
// Fused edge-softmax attention: warp per destination node, online softmax
// ---------------------------------------------------------------------------
__global__ void attn_kernel(const float* __restrict__ q, const float* __restrict__ k,
                            const float* __restrict__ v, const int* __restrict__ off,
                            const int* __restrict__ srcs, float* __restrict__ agg, int n)
{
    int node = blockIdx.x * 8 + threadIdx.y;
    if (node >= n) return;
    int lane = threadIdx.x;

    float4 kf = *(const float4*)(k + (size_t)node * DDIM + lane * 4);
    int beg = off[node], end = off[node + 1];

    float m = -INFINITY, ssum = 0.f;
    float4 acc = make_float4(0.f, 0.f, 0.f, 0.f);

    for (int j = beg; j < end; j++) {
        int s = srcs[j];
        float4 qa = *(const float4*)(q + (size_t)s * DDIM + lane * 4);
        float p = qa.x * kf.x + qa.y * kf.y + qa.z * kf.z + qa.w * kf.w;
        p += __shfl_xor_sync(0xffffffffu, p, 1);
        p += __shfl_xor_sync(0xffffffffu, p, 2);
        p *= 0.25f;  // 1/sqrt(HD=16)

        float mn = fmaxf(m, p);
        float scale = __expf(m - mn);
        float w = __expf(p - mn);
        ssum = ssum * scale + w;

        float4 vv = *(const float4*)(v + (size_t)s * DDIM + lane * 4);
        acc.x = acc.x * scale + w * vv.x;
        acc.y = acc.y * scale + w * vv.y;
        acc.z = acc.z * scale + w * vv.z;
        acc.w = acc.w * scale + w * vv.w;
        m = mn;
    }

    float inv = (end > beg) ? 1.f / ssum : 0.f;
    float4 outv;
    outv.x = acc.x * inv; outv.y = acc.y * inv;
    outv.z = acc.z * inv; outv.w = acc.w * inv;
    *(float4*)(agg + (size_t)node * DDIM + lane * 4) = outv;
}

// ---------------------------------------------------------------------------
// Host orchestration
// ---------------------------------------------------------------------------
extern "C" void kernel_launch(void* const* d_in, const int* in_sizes, int n_in,
                              void* d_out, int out_size)
{
    const float* x    = (const float*)d_in[0];
    const int*   esrc = (const int*)  d_in[1];
    const int*   edst = (const int*)  d_in[2];
    const float* Wi   = (const float*)d_in[3];
    const float* bi   = (const float*)d_in[4];
    const float* Wq   = (const float*)d_in[5];
    const float* bq   = (const float*)d_in[6];
    const float* Wk   = (const float*)d_in[7];
    const float* bk   = (const float*)d_in[8];
    const float* Wv   = (const float*)d_in[9];
    const float* bv   = (const float*)d_in[10];
    const float* Wo   = (const float*)d_in[11];
    const float* bo   = (const float*)d_in[12];
    const float* g1   = (const float*)d_in[13];
    const float* b1   = (const float*)d_in[14];
    const float* Wf1  = (const float*)d_in[15];
    const float* bf1  = (const float*)d_in[16];
    const float* Wf2  = (const float*)d_in[17];
    const float* bf2  = (const float*)d_in[18];
    const float* gout = (const float*)d_in[19];
    const float* boutg= (const float*)d_in[20];
    const float* Wout = (const float*)d_in[21];
    const float* bout = (const float*)d_in[22];

    const int Nn = in_sizes[0] / FIN;   // 50000
    const int Ee = in_sizes[1];         // 800000

    float *h, *ln, *q, *k, *v, *agg, *ff;
    int *deg, *cur, *off, *srcs;
    cudaGetSymbolAddress((void**)&h,    g_h);
    cudaGetSymbolAddress((void**)&ln,   g_ln);
    cudaGetSymbolAddress((void**)&q,    g_q);
    cudaGetSymbolAddress((void**)&k,    g_k);
    cudaGetSymbolAddress((void**)&v,    g_v);
    cudaGetSymbolAddress((void**)&agg,  g_agg);
    cudaGetSymbolAddress((void**)&ff,   g_ff);
    cudaGetSymbolAddress((void**)&deg,  g_deg);
    cudaGetSymbolAddress((void**)&cur,  g_cur);
    cudaGetSymbolAddress((void**)&off,  g_off);
    cudaGetSymbolAddress((void**)&srcs, g_srcs);

    const int mb = (Nn + 127) / 128;
    const dim3 gD(1, mb);            // N=128
    const dim3 gQKV(1, mb, 3);       // fused q,k,v
    const dim3 gF(2, mb);            // N=256
    const dim3 gC(1, mb);            // N=40
    const int lnBlocks = (Nn + 7) / 8;
    const dim3 warpRows(32, 8);
    const int eBlocks = (Ee + 255) / 256;
    const int nodeBlocks = (Nn + 7) / 8;

    // ---- CSR build (once; reused by all 5 layers)
    cudaMemsetAsync(deg, 0, Nn * sizeof(int));
    hist_kernel<<<eBlocks, 256>>>(edst, deg, Ee);
    scan_kernel<<<1, 1024>>>(deg, off, Nn);
    cudaMemcpyAsync(cur, off, Nn * sizeof(int), cudaMemcpyDeviceToDevice);
    scatter_kernel<<<eBlocks, 256>>>(esrc, edst, cur, srcs, Ee);

    // h = relu(x @ Wi + bi)
    gemm_tc_kernel<true, false><<<gD, 256>>>(x, Wi, bi, nullptr, h, Nn, DDIM, FIN);

    for (int i = 0; i < 5; i++) {
        const float* Wqi  = Wq  + (size_t)i * DDIM * DDIM;
        const float* Wki  = Wk  + (size_t)i * DDIM * DDIM;
        const float* Wvi  = Wv  + (size_t)i * DDIM * DDIM;
        const float* Woi  = Wo  + (size_t)i * DDIM * DDIM;
        const float* Wf1i = Wf1 + (size_t)i * DDIM * 2 * DDIM;
        const float* Wf2i = Wf2 + (size_t)i * 2 * DDIM * DDIM;

        ln_kernel<<<lnBlocks, warpRows>>>(h, g1 + i * DDIM, b1 + i * DDIM, ln, Nn);
        gemm_qkv_kernel<<<gQKV, 256>>>(ln, Wqi, Wki, Wvi,
                                       bq + i * DDIM, bk + i * DDIM, bv + i * DDIM,
                                       q, k, v, Nn);

        attn_kernel<<<nodeBlocks, warpRows>>>(q, k, v, off, srcs, agg, Nn);

        gemm_tc_kernel<false, true><<<gD, 256>>>(agg, Woi, bo + i * DDIM, h, h, Nn, DDIM, DDIM);

        ln_kernel<<<lnBlocks, warpRows>>>(h, g1 + i * DDIM, b1 + i * DDIM, ln, Nn);
        gemm_tc_kernel<true, false><<<gF, 256>>>(ln, Wf1i, bf1 + i * 2 * DDIM, nullptr, ff, Nn, 2 * DDIM, DDIM);
        gemm_tc_kernel<false, true><<<gD, 256>>>(ff, Wf2i, bf2 + i * DDIM, h, h, Nn, DDIM, 2 * DDIM);
    }

    // mid = h
    cudaMemcpyAsync(d_out, h, (size_t)Nn * DDIM * sizeof(float), cudaMemcpyDeviceToDevice);
    // out = LN(h) @ Wout + bout
    ln_kernel<<<lnBlocks, warpRows>>>(h, gout, boutg, ln, Nn);
    gemm_tc_kernel<false, false><<<gC, 256>>>(ln, Wout, bout, nullptr,
                                              (float*)d_out + (size_t)Nn * DDIM, Nn, NCLS, DDIM);
}

// round 5
// speedup vs baseline: 2.2539x; 1.1548x over previous
#include <cuda_runtime.h>
#include <math.h>
#include <stdint.h>

// ---------------------------------------------------------------------------
// Problem constants
// ---------------------------------------------------------------------------
#define NMAX 50000
#define EMAX 800000
#define DDIM 128
#define HEADS 8
#define FIN 256
#define NCLS 40

// ---------------------------------------------------------------------------
// Device scratch
// ---------------------------------------------------------------------------
__device__ float g_h  [NMAX * DDIM];
__device__ float g_ln [NMAX * DDIM];
__device__ float g_q  [NMAX * DDIM];
__device__ float g_k  [NMAX * DDIM];
__device__ float g_v  [NMAX * DDIM];
__device__ float g_agg[NMAX * DDIM];
__device__ float g_ff [NMAX * 2 * DDIM];
__device__ int   g_deg [NMAX];
__device__ int   g_cur [NMAX];
__device__ int   g_off [NMAX + 1];
__device__ int   g_srcs[EMAX];

// ---------------------------------------------------------------------------
// TF32 / async-copy helpers
// ---------------------------------------------------------------------------
__device__ __forceinline__ float f2tf32(float x)
{
    uint32_t r;
    asm("cvt.rna.tf32.f32 %0, %1;" : "=r"(r) : "f"(x));
    return __uint_as_float(r);
}

__device__ __forceinline__ void mma_tf32(float* d, const uint32_t* a, const uint32_t* b)
{
    asm volatile(
        "mma.sync.aligned.m16n8k8.row.col.f32.tf32.tf32.f32 "
        "{%0,%1,%2,%3}, {%4,%5,%6,%7}, {%8,%9}, {%0,%1,%2,%3};\n"
        : "+f"(d[0]), "+f"(d[1]), "+f"(d[2]), "+f"(d[3])
        : "r"(a[0]), "r"(a[1]), "r"(a[2]), "r"(a[3]), "r"(b[0]), "r"(b[1]));
}

__device__ __forceinline__ void cp_async16(uint32_t saddr, const void* gptr, bool pred)
{
    int bytes = pred ? 16 : 0;
    asm volatile("cp.async.cg.shared.global [%0], [%1], 16, %2;\n"
                 :: "r"(saddr), "l"(gptr), "r"(bytes));
}
#define CP_COMMIT() asm volatile("cp.async.commit_group;\n" ::: "memory")
#define CP_WAIT0()  asm volatile("cp.async.wait_group 0;\n" ::: "memory")

// ---------------------------------------------------------------------------
// Tensor-core GEMM (3xTF32 split), cp.async double-buffered, BK=32
// C[M,N] = op(A[M,K] @ B[K,N] + bias [+ Res]); K % 32 == 0, N % 4 == 0.
// Block 128x128, 8 warps (4M x 2N), warp tile 32x64 (2 x 8 m16n8 frags).
// Smem per stage: A fp32 [128][36], B fp32 [32][136].
// ---------------------------------------------------------------------------
#define BK 32
#define A_ST 36
#define B_ST 136
#define A_SZ (128 * A_ST)
#define B_SZ (BK * B_ST)
#define STAGE_SZ (A_SZ + B_SZ)
#define GEMM_SMEM_BYTES (2 * STAGE_SZ * (int)sizeof(float))

template <bool RELU, bool RES>
__device__ __forceinline__ void gemm_tc_body(
    float* __restrict__ sm,
    const float* __restrict__ A, const float* __restrict__ B,
    const float* __restrict__ bias, const float* __restrict__ Rsd,
    float* __restrict__ C, int M, int N, int K)
{
    const int tid  = threadIdx.x;
    const int lane = tid & 31;
    const int wid  = tid >> 5;
    const int g    = lane >> 2;
    const int c    = lane & 3;
    const int wm   = (wid >> 1) * 32;
    const int wn   = (wid & 1) * 64;

    const int row0 = blockIdx.y * 128;
    const int col0 = blockIdx.x * 128;

    const uint32_t smBase = (uint32_t)__cvta_generic_to_shared(sm);

    // Loader mapping (4 float4 chunks each for A and B per thread)
    const int laR = tid >> 1;             // A row pair base: rows laR, laR+... (id>>3 scheme below)
    (void)laR;

    // ---- async tile loaders
    auto loadA = [&](int st, int k0) {
        #pragma unroll
        for (int i = 0; i < 4; i++) {
            int id = tid + i * 256;
            int r  = id >> 3;             // 0..127
            int c4 = (id & 7) << 2;       // 0..28
            int ar = row0 + r;
            bool ok = ar < M;
            const float* gp = A + (size_t)(ok ? ar : 0) * K + k0 + c4;
            cp_async16(smBase + (uint32_t)((st * STAGE_SZ + r * A_ST + c4) * 4), gp, ok);
        }
    };
    auto loadB = [&](int st, int k0) {
        #pragma unroll
        for (int i = 0; i < 4; i++) {
            int id = tid + i * 256;
            int r  = id >> 5;             // 0..31
            int c4 = (id & 31) << 2;      // 0..124
            int nc = col0 + c4;
            bool ok = nc < N;             // N % 4 == 0 -> whole chunk valid
            const float* gp = B + (size_t)(k0 + r) * N + (ok ? nc : 0);
            cp_async16(smBase + (uint32_t)((st * STAGE_SZ + A_SZ + r * B_ST + c4) * 4), gp, ok);
        }
    };

    float acc[2][8][4] = {};

    const int KT = K / BK;
    loadA(0, 0);
    loadB(0, 0);
    CP_COMMIT();

    for (int kt = 0; kt < KT; kt++) {
        CP_WAIT0();
        __syncthreads();
        if (kt + 1 < KT) {
            int st = (kt + 1) & 1;
            loadA(st, (kt + 1) * BK);
            loadB(st, (kt + 1) * BK);
            CP_COMMIT();
        }

        const float* As_ = sm + (kt & 1) * STAGE_SZ;
        const float* Bs_ = As_ + A_SZ;

        #pragma unroll
        for (int kk = 0; kk < 4; kk++) {
            // A fragments: fp32 -> hi/lo split in registers
            uint32_t aH[2][4], aL[2][4];
            #pragma unroll
            for (int t = 0; t < 2; t++) {
                int r0 = (wm + 16 * t + g) * A_ST + kk * 8 + c;
                int r1 = (wm + 16 * t + g + 8) * A_ST + kk * 8 + c;
                float f0 = As_[r0],     f1 = As_[r1];
                float f2 = As_[r0 + 4], f3 = As_[r1 + 4];
                float h0 = f2tf32(f0), h1 = f2tf32(f1);
                float h2 = f2tf32(f2), h3 = f2tf32(f3);
                aH[t][0] = __float_as_uint(h0); aL[t][0] = __float_as_uint(f0 - h0);
                aH[t][1] = __float_as_uint(h1); aL[t][1] = __float_as_uint(f1 - h1);
                aH[t][2] = __float_as_uint(h2); aL[t][2] = __float_as_uint(f2 - h2);
                aH[t][3] = __float_as_uint(h3); aL[t][3] = __float_as_uint(f3 - h3);
            }
            #pragma unroll
            for (int jh = 0; jh < 2; jh++) {
                uint32_t bH[4][2], bL[4][2];
                #pragma unroll
                for (int j = 0; j < 4; j++) {
                    int n = wn + 8 * (jh * 4 + j) + g;
                    float f0 = Bs_[(kk * 8 + c) * B_ST + n];
                    float f1 = Bs_[(kk * 8 + 4 + c) * B_ST + n];
                    float h0 = f2tf32(f0), h1 = f2tf32(f1);
                    bH[j][0] = __float_as_uint(h0); bL[j][0] = __float_as_uint(f0 - h0);
                    bH[j][1] = __float_as_uint(h1); bL[j][1] = __float_as_uint(f1 - h1);
                }
                #pragma unroll
                for (int t = 0; t < 2; t++)
                    #pragma unroll
                    for (int j = 0; j < 4; j++) {
                        float* d = acc[t][jh * 4 + j];
                        mma_tf32(d, aH[t], bH[j]);
                        mma_tf32(d, aL[t], bH[j]);
                        mma_tf32(d, aH[t], bL[j]);
                    }
            }
        }
        __syncthreads();
    }

    // ---- Epilogue: thread owns rows {wm+16t+g, +8}, cols {wn+8j+2c, +1}
    #pragma unroll
    for (int t = 0; t < 2; t++) {
        #pragma unroll
        for (int rr = 0; rr < 2; rr++) {
            int r = row0 + wm + 16 * t + g + rr * 8;
            if (r >= M) continue;
            #pragma unroll
            for (int j = 0; j < 8; j++) {
                int cc = col0 + wn + 8 * j + 2 * c;
                if (cc >= N) continue;
                float v0 = acc[t][j][rr * 2 + 0] + bias[cc];
                float v1 = acc[t][j][rr * 2 + 1] + bias[cc + 1];
                if (RELU) { v0 = fmaxf(v0, 0.f); v1 = fmaxf(v1, 0.f); }
                if (RES) {
                    float2 rv = *(const float2*)(Rsd + (size_t)r * N + cc);
                    v0 += rv.x; v1 += rv.y;
                }
                float2 out; out.x = v0; out.y = v1;
                *(float2*)(C + (size_t)r * N + cc) = out;
            }
        }
    }
}

template <bool RELU, bool RES>
__global__ __launch_bounds__(256, 2) void gemm_tc_kernel(
    const float* __restrict__ A, const float* __restrict__ B,
    const float* __restrict__ bias, const float* __restrict__ Rsd,
    float* __restrict__ C, int M, int N, int K)
{
    extern __shared__ float sm[];
    gemm_tc_body<RELU, RES>(sm, A, B, bias, Rsd, C, M, N, K);
}

__global__ __launch_bounds__(256, 2) void gemm_qkv_kernel(
    const float* __restrict__ A,
    const float* __restrict__ Wq, const float* __restrict__ Wk, const float* __restrict__ Wv,
    const float* __restrict__ bq, const float* __restrict__ bk, const float* __restrict__ bv,
    float* __restrict__ q, float* __restrict__ k, float* __restrict__ v, int M)
{
    extern __shared__ float sm[];
    const float* B; const float* bias; float* C;
    if (blockIdx.z == 0)      { B = Wq; bias = bq; C = q; }
    else if (blockIdx.z == 1) { B = Wk; bias = bk; C = k; }
    else                      { B = Wv; bias = bv; C = v; }
    gemm_tc_body<false, false>(sm, A, B, bias, nullptr, C, M, DDIM, DDIM);
}

// ---------------------------------------------------------------------------
// LayerNorm over D=128: one warp per row, 8 rows per block
// ---------------------------------------------------------------------------
__global__ void ln_kernel(const float* __restrict__ X, const float* __restrict__ g,
                          const float* __restrict__ b, float* __restrict__ Y, int n)
{
    int row = blockIdx.x * 8 + threadIdx.y;
    if (row >= n) return;
    int lane = threadIdx.x;
    float4 x = *(const float4*)(X + (size_t)row * DDIM + lane * 4);
    float s  = x.x + x.y + x.z + x.w;
    float ss = x.x * x.x + x.y * x.y + x.z * x.z + x.w * x.w;
    #pragma unroll
    for (int o = 16; o > 0; o >>= 1) {
        s  += __shfl_xor_sync(0xffffffffu, s, o);
        ss += __shfl_xor_sync(0xffffffffu, ss, o);
    }
    float mu  = s * (1.f / DDIM);
    float var = ss * (1.f / DDIM) - mu * mu;
    float rstd = rsqrtf(var + 1e-5f);
    float4 gv = *(const float4*)(g + lane * 4);
    float4 bv = *(const float4*)(b + lane * 4);
    float4 y;
    y.x = (x.x - mu) * rstd * gv.x + bv.x;
    y.y = (x.y - mu) * rstd * gv.y + bv.y;
    y.z = (x.z - mu) * rstd * gv.z + bv.z;
    y.w = (x.w - mu) * rstd * gv.w + bv.w;
    *(float4*)(Y + (size_t)row * DDIM + lane * 4) = y;
}

// ---------------------------------------------------------------------------
// CSR build (edges grouped by destination) — once per launch
// ---------------------------------------------------------------------------
__global__ void hist_kernel(const int* __restrict__ dst, int* __restrict__ deg, int E)
{
    int t = blockIdx.x * blockDim.x + threadIdx.x;
    if (t < E) atomicAdd(&deg[dst[t]], 1);
}

__global__ void scan_kernel(const int* __restrict__ deg, int* __restrict__ off, int n)
{
    const int T = 1024;
    __shared__ int sm[T];
    int t = threadIdx.x;
    int chunk = (n + T - 1) / T;
    int b = t * chunk;
    int e = min(n, b + chunk);
    int s = 0;
    for (int i = b; i < e; i++) s += deg[i];
    sm[t] = s;
    __syncthreads();
    for (int o = 1; o < T; o <<= 1) {
        int add = (t >= o) ? sm[t - o] : 0;
        __syncthreads();
        sm[t] += add;
        __syncthreads();
    }
    int excl = (t > 0) ? sm[t - 1] : 0;
    for (int i = b; i < e; i++) { off[i] = excl; excl += deg[i]; }
    if (t == T - 1) off[n] = excl;
}

__global__ void scatter_kernel(const int* __restrict__ src, const int* __restrict__ dst,
                               int* __restrict__ cur, int* __restrict__ srcs, int E)
{
    int t = blockIdx.x * blockDim.x + threadIdx.x;
    if (t < E) {
        int p = atomicAdd(&cur[dst[t]], 1);
        srcs[p] = src[t];
    }
}

// ---------------------------------------------------------------------------
// Fused edge-softmax attention: warp per destination node, online softmax
// ---------------------------------------------------------------------------
__global__ void attn_kernel(const float* __restrict__ q, const float* __restrict__ k,
                            const float* __restrict__ v, const int* __restrict__ off,
                            const int* __restrict__ srcs, float* __restrict__ agg, int n)
{
    int node = blockIdx.x * 8 + threadIdx.y;
    if (node >= n) return;
    int lane = threadIdx.x;

    float4 kf = *(const float4*)(k + (size_t)node * DDIM + lane * 4);
    int beg = off[node], end = off[node + 1];

    float m = -INFINITY, ssum = 0.f;
    float4 acc = make_float4(0.f, 0.f, 0.f, 0.f);

    for (int j = beg; j < end; j++) {
        int s = srcs[j];
        float4 qa = *(const float4*)(q + (size_t)s * DDIM + lane * 4);
        float p = qa.x * kf.x + qa.y * kf.y + qa.z * kf.z + qa.w * kf.w;
        p += __shfl_xor_sync(0xffffffffu, p, 1);
        p += __shfl_xor_sync(0xffffffffu, p, 2);
        p *= 0.25f;  // 1/sqrt(HD=16)

        float mn = fmaxf(m, p);
        float scale = __expf(m - mn);
        float w = __expf(p - mn);
        ssum = ssum * scale + w;

        float4 vv = *(const float4*)(v + (size_t)s * DDIM + lane * 4);
        acc.x = acc.x * scale + w * vv.x;
        acc.y = acc.y * scale + w * vv.y;
        acc.z = acc.z * scale + w * vv.z;
        acc.w = acc.w * scale + w * vv.w;
        m = mn;
    }

    float inv = (end > beg) ? 1.f / ssum : 0.f;
    float4 outv;
    outv.x = acc.x * inv; outv.y = acc.y * inv;
    outv.z = acc.z * inv; outv.w = acc.w * inv;
    *(float4*)(agg + (size_t)node * DDIM + lane * 4) = outv;
}

// ---------------------------------------------------------------------------
// Host orchestration
// ---------------------------------------------------------------------------
extern "C" void kernel_launch(void* const* d_in, const int* in_sizes, int n_in,
                              void* d_out, int out_size)
{
    const float* x    = (const float*)d_in[0];
    const int*   esrc = (const int*)  d_in[1];
    const int*   edst = (const int*)  d_in[2];
    const float* Wi   = (const float*)d_in[3];
    const float* bi   = (const float*)d_in[4];
    const float* Wq   = (const float*)d_in[5];
    const float* bq   = (const float*)d_in[6];
    const float* Wk   = (const float*)d_in[7];
    const float* bk   = (const float*)d_in[8];
    const float* Wv   = (const float*)d_in[9];
    const float* bv   = (const float*)d_in[10];
    const float* Wo   = (const float*)d_in[11];
    const float* bo   = (const float*)d_in[12];
    const float* g1   = (const float*)d_in[13];
    const float* b1   = (const float*)d_in[14];
    const float* Wf1  = (const float*)d_in[15];
    const float* bf1  = (const float*)d_in[16];
    const float* Wf2  = (const float*)d_in[17];
    const float* bf2  = (const float*)d_in[18];
    const float* gout = (const float*)d_in[19];
    const float* boutg= (const float*)d_in[20];
    const float* Wout = (const float*)d_in[21];
    const float* bout = (const float*)d_in[22];

    const int Nn = in_sizes[0] / FIN;   // 50000
    const int Ee = in_sizes[1];         // 800000

    float *h, *ln, *q, *k, *v, *agg, *ff;
    int *deg, *cur, *off, *srcs;
    cudaGetSymbolAddress((void**)&h,    g_h);
    cudaGetSymbolAddress((void**)&ln,   g_ln);
    cudaGetSymbolAddress((void**)&q,    g_q);
    cudaGetSymbolAddress((void**)&k,    g_k);
    cudaGetSymbolAddress((void**)&v,    g_v);
    cudaGetSymbolAddress((void**)&agg,  g_agg);
    cudaGetSymbolAddress((void**)&ff,   g_ff);
    cudaGetSymbolAddress((void**)&deg,  g_deg);
    cudaGetSymbolAddress((void**)&cur,  g_cur);
    cudaGetSymbolAddress((void**)&off,  g_off);
    cudaGetSymbolAddress((void**)&srcs, g_srcs);

    // Opt-in to >48KB dynamic smem (idempotent; not a stream op)
    cudaFuncSetAttribute(gemm_tc_kernel<false, false>, cudaFuncAttributeMaxDynamicSharedMemorySize, GEMM_SMEM_BYTES);
    cudaFuncSetAttribute(gemm_tc_kernel<true,  false>, cudaFuncAttributeMaxDynamicSharedMemorySize, GEMM_SMEM_BYTES);
    cudaFuncSetAttribute(gemm_tc_kernel<false, true>,  cudaFuncAttributeMaxDynamicSharedMemorySize, GEMM_SMEM_BYTES);
    cudaFuncSetAttribute(gemm_qkv_kernel,              cudaFuncAttributeMaxDynamicSharedMemorySize, GEMM_SMEM_BYTES);

    const int mb = (Nn + 127) / 128;
    const dim3 gD(1, mb);            // N=128
    const dim3 gQKV(1, mb, 3);       // fused q,k,v
    const dim3 gF(2, mb);            // N=256
    const dim3 gC(1, mb);            // N=40
    const int lnBlocks = (Nn + 7) / 8;
    const dim3 warpRows(32, 8);
    const int eBlocks = (Ee + 255) / 256;
    const int nodeBlocks = (Nn + 7) / 8;

    // ---- CSR build (once; reused by all 5 layers)
    cudaMemsetAsync(deg, 0, Nn * sizeof(int));
    hist_kernel<<<eBlocks, 256>>>(edst, deg, Ee);
    scan_kernel<<<1, 1024>>>(deg, off, Nn);
    cudaMemcpyAsync(cur, off, Nn * sizeof(int), cudaMemcpyDeviceToDevice);
    scatter_kernel<<<eBlocks, 256>>>(esrc, edst, cur, srcs, Ee);

    // h = relu(x @ Wi + bi)
    gemm_tc_kernel<true, false><<<gD, 256, GEMM_SMEM_BYTES>>>(x, Wi, bi, nullptr, h, Nn, DDIM, FIN);

    for (int i = 0; i < 5; i++) {
        const float* Wqi  = Wq  + (size_t)i * DDIM * DDIM;
        const float* Wki  = Wk  + (size_t)i * DDIM * DDIM;
        const float* Wvi  = Wv  + (size_t)i * DDIM * DDIM;
        const float* Woi  = Wo  + (size_t)i * DDIM * DDIM;
        const float* Wf1i = Wf1 + (size_t)i * DDIM * 2 * DDIM;
        const float* Wf2i = Wf2 + (size_t)i * 2 * DDIM * DDIM;

        ln_kernel<<<lnBlocks, warpRows>>>(h, g1 + i * DDIM, b1 + i * DDIM, ln, Nn);
        gemm_qkv_kernel<<<gQKV, 256, GEMM_SMEM_BYTES>>>(ln, Wqi, Wki, Wvi,
                                        bq + i * DDIM, bk + i * DDIM, bv + i * DDIM,
                                        q, k, v, Nn);

        attn_kernel<<<nodeBlocks, warpRows>>>(q, k, v, off, srcs, agg, Nn);

        gemm_tc_kernel<false, true><<<gD, 256, GEMM_SMEM_BYTES>>>(agg, Woi, bo + i * DDIM, h, h, Nn, DDIM, DDIM);

        ln_kernel<<<lnBlocks, warpRows>>>(h, g1 + i * DDIM, b1 + i * DDIM, ln, Nn);
        gemm_tc_kernel<true, false><<<gF, 256, GEMM_SMEM_BYTES>>>(ln, Wf1i, bf1 + i * 2 * DDIM, nullptr, ff, Nn, 2 * DDIM, DDIM);
        gemm_tc_kernel<false, true><<<gD, 256, GEMM_SMEM_BYTES>>>(ff, Wf2i, bf2 + i * DDIM, h, h, Nn, DDIM, 2 * DDIM);
    }

    // mid = h
    cudaMemcpyAsync(d_out, h, (size_t)Nn * DDIM * sizeof(float), cudaMemcpyDeviceToDevice);
    // out = LN(h) @ Wout + bout
    ln_kernel<<<lnBlocks, warpRows>>>(h, gout, boutg, ln, Nn);
    gemm_tc_kernel<false, false><<<gC, 256, GEMM_SMEM_BYTES>>>(ln, Wout, bout, nullptr,
                                              (float*)d_out + (size_t)Nn * DDIM, Nn, NCLS, DDIM);
}